// round 7
// baseline (speedup 1.0000x reference)
#include <cuda_runtime.h>
#include <math.h>

#define Nn 4
#define Cc 19
#define HWp (768*768)

// ---------------- device scratch (no allocations allowed) ----------------
__device__ unsigned g_h1[Nn][Cc];               // per-image histogram of segmask
__device__ unsigned g_h2[Nn][Cc];               // per-image histogram of edge-gated target
__device__ unsigned long long g_poscnt;         // # of edgemask==1 pixels (global)
__device__ double g_bce_pos, g_bce_neg;         // BCE sums over pos / neg pixels
__device__ float g_w1[Nn][Cc], g_w2[Nn][Cc];    // class weights
__device__ double g_num1[Nn], g_den1[Nn];       // seg loss accumulators
__device__ double g_num2[Nn], g_den2[Nn];       // attention loss accumulators

// ---------------- zero scratch (graph-replay determinism) ----------------
__global__ void zero_k() {
    int t = threadIdx.x;
    if (t < Nn * Cc) { (&g_h1[0][0])[t] = 0u; (&g_h2[0][0])[t] = 0u; }
    if (t < Nn) { g_num1[t] = 0.0; g_den1[t] = 0.0; g_num2[t] = 0.0; g_den2[t] = 0.0; }
    if (t == 0) { g_poscnt = 0ull; g_bce_pos = 0.0; g_bce_neg = 0.0; }
}

// ---------------- pass 1: histograms + BCE partials ----------------
// grid: (HWp/1024, Nn), block 256, 4 pixels/thread via vector loads
__global__ void __launch_bounds__(256) pass1_k(const float* __restrict__ edgein,
                                               const int*   __restrict__ segmask,
                                               const int*   __restrict__ edgemask) {
    __shared__ unsigned sh1[Cc], sh2[Cc];
    __shared__ float rbp[8], rbn[8];
    __shared__ int   rpc[8];
    const int tid = threadIdx.x;
    if (tid < Cc) { sh1[tid] = 0u; sh2[tid] = 0u; }
    __syncthreads();

    const int n = blockIdx.y;
    const size_t base = (size_t)n * HWp + ((size_t)blockIdx.x * blockDim.x + tid) * 4;
    const int4   sm = *reinterpret_cast<const int4*>(segmask + base);
    const float4 ev = *reinterpret_cast<const float4*>(edgein + base);
    const int4   em = *reinterpret_cast<const int4*>(edgemask + base);

    int   s[4]  = { sm.x, sm.y, sm.z, sm.w };
    float x[4]  = { ev.x, ev.y, ev.z, ev.w };
    int   tm[4] = { em.x, em.y, em.z, em.w };

    float bp = 0.f, bn = 0.f; int pc = 0;
#pragma unroll
    for (int i = 0; i < 4; i++) {
        // histc semantics: count only labels in [0, C)
        if ((unsigned)s[i] < (unsigned)Cc) {
            atomicAdd(&sh1[s[i]], 1u);
            if (x[i] > 0.8f) atomicAdd(&sh2[s[i]], 1u);  // attention target keeps label iff edge > thresh
        }
        // stable BCE-with-logits: max(x,0) - x*t + log1p(exp(-|x|))
        float xv = x[i];
        float b = fmaxf(xv, 0.f) - xv * (float)tm[i] + log1pf(__expf(-fabsf(xv)));
        if (tm[i] == 1) { bp += b; pc++; } else { bn += b; }
    }

    // warp reduce
#pragma unroll
    for (int o = 16; o; o >>= 1) {
        bp += __shfl_down_sync(0xffffffffu, bp, o);
        bn += __shfl_down_sync(0xffffffffu, bn, o);
        pc += __shfl_down_sync(0xffffffffu, pc, o);
    }
    const int w = tid >> 5, l = tid & 31;
    if (l == 0) { rbp[w] = bp; rbn[w] = bn; rpc[w] = pc; }
    __syncthreads();

    if (tid < Cc) {
        if (sh1[tid]) atomicAdd(&g_h1[n][tid], sh1[tid]);
        if (sh2[tid]) atomicAdd(&g_h2[n][tid], sh2[tid]);
    }
    if (tid == 0) {
        float a = 0.f, b = 0.f; int c = 0;
#pragma unroll
        for (int i = 0; i < 8; i++) { a += rbp[i]; b += rbn[i]; c += rpc[i]; }
        atomicAdd(&g_bce_pos, (double)a);
        atomicAdd(&g_bce_neg, (double)b);
        atomicAdd(&g_poscnt, (unsigned long long)c);
    }
}

// ---------------- weights from histograms ----------------
__global__ void weights_k() {
    __shared__ float s1[Nn], s2[Nn];
    int tid = threadIdx.x;
    if (tid < Nn) {
        float a = 0.f, b = 0.f;
        for (int c = 0; c < Cc; c++) { a += (float)g_h1[tid][c]; b += (float)g_h2[tid][c]; }
        s1[tid] = a; s2[tid] = b;
    }
    __syncthreads();
    if (tid < Nn * Cc) {
        int n = tid / Cc, c = tid % Cc;
        unsigned c1 = g_h1[n][c];
        g_w1[n][c] = c1 ? ((1.f - (float)c1 / s1[n]) + 1.f) : 1.f;   // UPPER_BOUND = 1
        unsigned c2 = g_h2[n][c];
        g_w2[n][c] = c2 ? ((1.f - (float)c2 / s2[n]) + 1.f) : 1.f;
    }
}

// ---------------- pass 2: logsumexp + weighted NLL (seg + attention) ----------------
// grid: (HWp/256, Nn), block 256, 1 pixel/thread; 19 coalesced channel loads
__global__ void __launch_bounds__(256) pass2_k(const float* __restrict__ segin,
                                               const float* __restrict__ edgein,
                                               const int*   __restrict__ segmask) {
    __shared__ float sw1[Cc], sw2[Cc];
    __shared__ float red[8][4];
    const int tid = threadIdx.x;
    const int n = blockIdx.y;
    if (tid < Cc) { sw1[tid] = g_w1[n][tid]; sw2[tid] = g_w2[n][tid]; }
    __syncthreads();

    const int p = blockIdx.x * 256 + tid;           // grid exactly covers HWp
    int t = segmask[(size_t)n * HWp + p];
    t = t < 0 ? 0 : (t > Cc - 1 ? Cc - 1 : t);      // clip like reference

    const float* b = segin + (size_t)n * Cc * HWp + p;
    float xs[Cc];
    float m = -3.4e38f, xt = 0.f;
#pragma unroll
    for (int c = 0; c < Cc; c++) {
        float v = __ldg(b + (size_t)c * HWp);
        xs[c] = v;
        m = fmaxf(m, v);
        if (c == t) xt = v;                         // predicated select, no spill
    }
    float s = 0.f;
#pragma unroll
    for (int c = 0; c < Cc; c++) s += __expf(xs[c] - m);
    const float nll = m + __logf(s) - xt;           // -log_softmax[target]

    float w1 = sw1[t];
    float num1 = w1 * nll, den1 = w1, num2 = 0.f, den2 = 0.f;
    float e = edgein[(size_t)n * HWp + p];
    if (e > 0.8f) { float w2 = sw2[t]; num2 = w2 * nll; den2 = w2; }

#pragma unroll
    for (int o = 16; o; o >>= 1) {
        num1 += __shfl_down_sync(0xffffffffu, num1, o);
        den1 += __shfl_down_sync(0xffffffffu, den1, o);
        num2 += __shfl_down_sync(0xffffffffu, num2, o);
        den2 += __shfl_down_sync(0xffffffffu, den2, o);
    }
    const int w = tid >> 5, l = tid & 31;
    if (l == 0) { red[w][0] = num1; red[w][1] = den1; red[w][2] = num2; red[w][3] = den2; }
    __syncthreads();
    if (tid == 0) {
        float a = 0.f, bb = 0.f, c = 0.f, d = 0.f;
#pragma unroll
        for (int i = 0; i < 8; i++) { a += red[i][0]; bb += red[i][1]; c += red[i][2]; d += red[i][3]; }
        atomicAdd(&g_num1[n], (double)a);
        atomicAdd(&g_den1[n], (double)bb);
        atomicAdd(&g_num2[n], (double)c);
        atomicAdd(&g_den2[n], (double)d);
    }
}

// ---------------- finalize ----------------
__global__ void final_k(float* out) {
    double loss = 0.0;
    for (int n = 0; n < Nn; n++) loss += 1.0 * (g_num1[n] / g_den1[n]);   // SEG_W = 1.0
    for (int n = 0; n < Nn; n++) loss += 0.1 * (g_num2[n] / g_den2[n]);   // ATT_W = 0.1
    const double total = (double)Nn * (double)HWp;                         // all pixels are pos or neg
    const double pos = (double)g_poscnt;
    const double neg = total - pos;
    const double bce_sum = (neg / total) * g_bce_pos + (pos / total) * g_bce_neg;
    loss += 0.3 * (bce_sum / total);                                       // EDGE_W = 0.3, mean over N*H*W
    out[0] = (float)loss;
}

// ---------------- launch ----------------
extern "C" void kernel_launch(void* const* d_in, const int* in_sizes, int n_in,
                              void* d_out, int out_size) {
    const float* segin    = (const float*)d_in[0];
    const float* edgein   = (const float*)d_in[1];
    const int*   segmask  = (const int*)d_in[2];
    const int*   edgemask = (const int*)d_in[3];
    (void)in_sizes; (void)n_in; (void)out_size;

    zero_k<<<1, 128>>>();
    pass1_k<<<dim3(HWp / (256 * 4), Nn), 256>>>(edgein, segmask, edgemask);
    weights_k<<<1, 128>>>();
    pass2_k<<<dim3(HWp / 256, Nn), 256>>>(segin, edgein, segmask);
    final_k<<<1, 1>>>((float*)d_out);
}